// round 12
// baseline (speedup 1.0000x reference)
#include <cuda_runtime.h>

#define EPSF 1e-10f
#define MAXP 8192

static __device__ double g_partials[MAXP];
static __device__ unsigned g_count;   // zero-init; reset by last block each launch

__global__ void __launch_bounds__(256) loss_k(
    const float* __restrict__ preds,
    const long long* __restrict__ labs,
    const int* __restrict__ cen,
    int N, float* __restrict__ out)
{
    const int tid = threadIdx.x;
    const int lane = tid & 31;
    const int sub = tid & 3;                         // lane within 4-lane group
    const unsigned gmask = 0xfu << (lane & 28);      // this group's mask
    const int i = (blockIdx.x * blockDim.x + tid) >> 2;   // example index

    double local = 0.0;

    if (i < N) {
        // metadata (all 4 lanes load same addrs -> broadcast sectors)
        const int c0 = cen[i];
        const int c1 = cen[i + N];
        const long long la = labs[i];        // mod0 label == labs0 (drives t1)
        const long long lb = labs[i + N];

        const float* p0 = preds + (size_t)i * 100;
        const float* p1 = p0 + (size_t)N * 100;

        // uncensored gathers: spread across two lanes for parallelism
        if (c0 == 0 && sub == 0)
            local += (double)__logf(__ldg(p0 + (int)la) + EPSF);
        if (c1 == 0 && sub == 1)
            local += (double)__logf(__ldg(p1 + (int)lb) + EPSF);

        const bool d0 = (c0 == 1);
        const bool d1 = (c1 == 1);
        if (d0 | d1) {                        // group-uniform branch
            const int t1 = (int)la + 1;       // 1..100
            const int a0 = t1 >> 2;           // first float4 containing t1
            const int r = t1 & 3;
            float s0 = 0.f, s1 = 0.f;
            const float4* q0 = (const float4*)p0;   // 400B rows -> 16B aligned
            const float4* q1 = (const float4*)p1;
            for (int j = a0 + sub; j < 25; j += 4) {
                float4 u0 = d0 ? __ldg(q0 + j) : make_float4(0.f,0.f,0.f,0.f);
                float4 u1 = d1 ? __ldg(q1 + j) : make_float4(0.f,0.f,0.f,0.f);
                if (j == a0 && r) {           // mask head elements below t1
                    if (r > 0) { u0.x = 0.f; u1.x = 0.f; }
                    if (r > 1) { u0.y = 0.f; u1.y = 0.f; }
                    if (r > 2) { u0.z = 0.f; u1.z = 0.f; }
                }
                s0 += (u0.x + u0.y) + (u0.z + u0.w);
                s1 += (u1.x + u1.y) + (u1.z + u1.w);
            }
            // reduce across the 4-lane group (group-local mask: warp may be
            // divergent across groups here)
            s0 += __shfl_down_sync(gmask, s0, 2, 4);
            s1 += __shfl_down_sync(gmask, s1, 2, 4);
            s0 += __shfl_down_sync(gmask, s0, 1, 4);
            s1 += __shfl_down_sync(gmask, s1, 1, 4);
            if (sub == 0) {
                if (d0) local += 0.5 * (double)__logf(s0 + EPSF);
                if (d1) local += 0.5 * (double)__logf(s1 + EPSF);
            }
        }
    }

    // block reduction (doubles) — warp-uniform from here
    #pragma unroll
    for (int o = 16; o; o >>= 1)
        local += __shfl_down_sync(0xffffffffu, local, o);

    __shared__ double wsum[8];
    const int wib = tid >> 5;
    if (lane == 0) wsum[wib] = local;
    __syncthreads();

    if (wib == 0) {
        double v = (lane < 8) ? wsum[lane] : 0.0;
        #pragma unroll
        for (int o = 4; o; o >>= 1)
            v += __shfl_down_sync(0xffffffffu, v, o);
        if (lane == 0) g_partials[blockIdx.x] = v;
    }

    // last-block-done final reduction (no second kernel)
    __shared__ bool isLast;
    if (tid == 0) {
        __threadfence();
        unsigned c = atomicAdd(&g_count, 1u);
        isLast = (c == gridDim.x - 1);
    }
    __syncthreads();

    if (isLast) {   // block-uniform
        double v = 0.0;
        for (int k = tid; k < (int)gridDim.x; k += blockDim.x)
            v += g_partials[k];
        #pragma unroll
        for (int o = 16; o; o >>= 1)
            v += __shfl_down_sync(0xffffffffu, v, o);
        if (lane == 0) wsum[wib] = v;
        __syncthreads();
        if (tid == 0) {
            double t = 0.0;
            #pragma unroll
            for (int w = 0; w < 8; ++w) t += wsum[w];
            *out = (float)(-t / (double)N);
            g_count = 0;                      // reset for next graph replay
        }
    }
}

extern "C" void kernel_launch(void* const* d_in, const int* in_sizes, int n_in,
                              void* d_out, int out_size)
{
    const float* preds = (const float*)d_in[0];        // [2, N, 100] f32
    const long long* labs = (const long long*)d_in[1]; // [2, N] i64
    const int* cen = (const int*)d_in[2];              // [2, N] i32

    const int rows = in_sizes[1];      // 2*N
    const int N = rows / 2;

    int nblocks = (N * 4 + 255) / 256;   // 4 lanes per example
    if (nblocks > MAXP) nblocks = MAXP;

    loss_k<<<nblocks, 256>>>(preds, labs, cen, N, (float*)d_out);
}

// round 14
// speedup vs baseline: 1.8724x; 1.8724x over previous
#include <cuda_runtime.h>

#define EPSF 1e-10f
#define MAXP 4096

static __device__ double g_partials[MAXP];
static __device__ unsigned g_count;   // zero-init; reset by last block each launch

__global__ void __launch_bounds__(256) loss_k(
    const float* __restrict__ preds,
    const long long* __restrict__ labs,
    const int* __restrict__ cen,
    int N, int rows, float* __restrict__ out)
{
    const int tid = threadIdx.x;
    const int row = blockIdx.x * blockDim.x + tid;
    double local = 0.0;

    if (row < rows) {
        // independent scalar loads up front
        const int c = cen[row];
        const long long lself = labs[row];
        const long long l0 = (row < N) ? lself : labs[row - N];

        const float* prow = preds + (size_t)row * 100;

        if (c == 0) {
            // uncensored: log p[row, lab]
            local = (double)__logf(__ldg(prow + (int)lself) + EPSF);
        } else {
            // censored: s = sum_{j>=t1} p. Rows are softmax outputs (sum==1),
            // so read the SHORTER side: suffix if t1>50 (exact, handles small s),
            // else prefix and s = 1 - prefix (s >= ~0.5 there, error ~1e-7).
            const int t1 = (int)l0 + 1;              // 1..100
            const bool sfx = (t1 > 50);
            const int lo4 = sfx ? (t1 >> 2) : 0;
            const int hi4 = sfx ? 25 : ((t1 + 3) >> 2);
            const int r = t1 & 3;

            const float4* p4 = (const float4*)prow;  // 400B rows -> 16B aligned
            float acc = 0.0f;
            #pragma unroll
            for (int k = 0; k < 13; ++k) {           // window length <= 13 float4s
                const int j = lo4 + k;
                float4 u = (j < hi4) ? __ldg(p4 + j)
                                     : make_float4(0.f, 0.f, 0.f, 0.f);
                if (sfx) {
                    if (j == lo4 && r) {             // head mask: drop idx < t1
                        if (r > 0) u.x = 0.f;
                        if (r > 1) u.y = 0.f;
                        if (r > 2) u.z = 0.f;
                    }
                } else {
                    if (j == hi4 - 1 && r) {         // tail mask: drop idx >= t1
                        if (r < 2) u.y = 0.f;
                        if (r < 3) u.z = 0.f;
                        u.w = 0.f;                   // r in 1..3 -> w always dropped
                    }
                }
                acc += (u.x + u.y) + (u.z + u.w);
            }
            const float s = sfx ? acc : fmaxf(1.0f - acc, 0.0f);
            local = 0.5 * (double)__logf(s + EPSF);
        }
    }

    // block reduction (doubles)
    #pragma unroll
    for (int o = 16; o; o >>= 1)
        local += __shfl_down_sync(0xffffffffu, local, o);

    __shared__ double wsum[8];
    const int lane = tid & 31;
    const int wib = tid >> 5;
    if (lane == 0) wsum[wib] = local;
    __syncthreads();

    if (wib == 0) {
        double v = (lane < 8) ? wsum[lane] : 0.0;
        #pragma unroll
        for (int o = 4; o; o >>= 1)
            v += __shfl_down_sync(0xffffffffu, v, o);
        if (lane == 0) g_partials[blockIdx.x] = v;
    }

    // last-block-done final reduction (no second kernel)
    __shared__ bool isLast;
    if (tid == 0) {
        __threadfence();
        unsigned c = atomicAdd(&g_count, 1u);
        isLast = (c == gridDim.x - 1);
    }
    __syncthreads();

    if (isLast) {   // block-uniform
        double v = 0.0;
        for (int k = tid; k < (int)gridDim.x; k += blockDim.x)
            v += g_partials[k];
        #pragma unroll
        for (int o = 16; o; o >>= 1)
            v += __shfl_down_sync(0xffffffffu, v, o);
        if (lane == 0) wsum[wib] = v;
        __syncthreads();
        if (tid == 0) {
            double t = 0.0;
            #pragma unroll
            for (int w = 0; w < 8; ++w) t += wsum[w];
            *out = (float)(-t / (double)N);
            g_count = 0;                      // reset for next graph replay
        }
    }
}

extern "C" void kernel_launch(void* const* d_in, const int* in_sizes, int n_in,
                              void* d_out, int out_size)
{
    const float* preds = (const float*)d_in[0];        // [2, N, 100] f32
    const long long* labs = (const long long*)d_in[1]; // [2, N] i64
    const int* cen = (const int*)d_in[2];              // [2, N] i32

    const int rows = in_sizes[1];      // 2*N
    const int N = rows / 2;

    int nblocks = (rows + 255) / 256;  // ~3907
    if (nblocks > MAXP) nblocks = MAXP;

    loss_k<<<nblocks, 256>>>(preds, labs, cen, N, rows, (float*)d_out);
}